// round 12
// baseline (speedup 1.0000x reference)
#include <cuda_runtime.h>
#include <math.h>

#define DIN    64
#define FDIM   256
#define NH     4
#define NMAXC  50000
#define MAXL1  4096
#define MAXT   (MAXL1 + 1)
#define MAXE1  32768
#define MAXU   (MAXT + MAXE1)
#define MAXDEG 512
#define NBW    1568
#define GRID   148
#define TPB    256
#define NSUB   8
#define SUBSTR 64                       // 64 ints = 256B stride per sub-counter

#define VREAD(x) (*(volatile int*)&(x))

// ---------------- scratch (static device globals, zero-initialized) ---------
__device__ int      g_uslot[NMAXC];     // 0=free, -1=pending, k+1 = slot k
__device__ unsigned g_tbit[NBW];
__device__ int      g_l1_src[MAXL1];
__device__ int      g_l1_us[MAXL1];
__device__ int      g_e1_dstn[MAXE1];
__device__ int      g_e1_dst[MAXE1];
__device__ int      g_e1_src[MAXE1];
__device__ int      g_e1_us[MAXE1];
__device__ int      g_ulist[MAXU];
__device__ int      g_cnt[4];           // 0=l1 1=tgt 2=u 3=e1 (self-cleaned)
__device__ __align__(16) float g_h0[MAXU][FDIM];
__device__ float    g_al0[MAXU][2*NH];
__device__ __align__(16) float g_h1[MAXT][FDIM];
__device__ float    g_al1[MAXT][2*NH];
__device__ float    g_mlp[DIN];
__device__ int      g_barc_sub[NSUB * SUBSTR];  // spread arrival counters
__device__ int      g_barm;             // master counter (8 arrivals)
__device__ int      g_barg;             // barrier generation (monotonic)

// ---------------- helpers ---------------------------------------------------
__device__ __forceinline__ float warp_sum(float v) {
    #pragma unroll
    for (int o = 16; o; o >>= 1) v += __shfl_xor_sync(0xffffffffu, v, o);
    return v;
}
__device__ __forceinline__ float warp_max(float v) {
    #pragma unroll
    for (int o = 16; o; o >>= 1) v = fmaxf(v, __shfl_xor_sync(0xffffffffu, v, o));
    return v;
}
__device__ __forceinline__ float lrelu(float x) { return x > 0.f ? x : 0.2f * x; }

__device__ __forceinline__ void s1_hit(int d, int tgt, const int* __restrict__ src, int e) {
    if (d == tgt) {
        int p = atomicAdd(&g_cnt[0], 1);
        if (p < MAXL1) g_l1_src[p] = src[e];
    }
}
__device__ __forceinline__ void s2_hit(int d, int N, const int* __restrict__ src, int e) {
    if ((unsigned)d < (unsigned)N) {
        if ((g_tbit[d >> 5] >> (d & 31)) & 1u) {
            int p = atomicAdd(&g_cnt[3], 1);
            if (p < MAXE1) { g_e1_dstn[p] = d; g_e1_src[p] = src[e]; }
        }
    }
}

// Grid barrier with 2-level spread arrival: CTAs arrive on 8 independent
// L2 lines; subgroup-last bumps master; master-last is the tail CTA and runs
// TAILCODE (block-parallel) before releasing everyone via g_barg.
#define GBAR(...) do {                                                         \
    __syncthreads();                                                           \
    if (threadIdx.x == 0) {                                                    \
        __threadfence();                                                       \
        s_gen = VREAD(g_barg);                                                 \
        int sg = bid & (NSUB - 1);                                             \
        int expect = (sg < (GRID & (NSUB - 1))) ? (GRID / NSUB + 1)            \
                                                : (GRID / NSUB);               \
        int tf = 0;                                                            \
        if (atomicAdd(&g_barc_sub[sg * SUBSTR], 1) == expect - 1) {            \
            if (atomicAdd(&g_barm, 1) == NSUB - 1) tf = 1;                     \
        }                                                                      \
        s_tailf = tf;                                                          \
        if (tf) __threadfence();                                               \
    }                                                                          \
    __syncthreads();                                                           \
    if (s_tailf) {                                                             \
        { __VA_ARGS__ }                                                        \
        __syncthreads();                                                       \
        if (threadIdx.x == 0) {                                                \
            for (int sg = 0; sg < NSUB; sg++) g_barc_sub[sg * SUBSTR] = 0;     \
            g_barm = 0;                                                        \
            __threadfence();                                                   \
            *(volatile int*)&g_barg = s_gen + 1;                               \
        }                                                                      \
        __syncthreads();                                                       \
    } else {                                                                   \
        if (threadIdx.x == 0) {                                                \
            while (VREAD(g_barg) == s_gen) __nanosleep(32);                    \
            __threadfence();                                                   \
        }                                                                      \
        __syncthreads();                                                       \
    }                                                                          \
} while (0)

// ---------------- the megakernel --------------------------------------------
__global__ void __launch_bounds__(TPB) mega(
    const int* __restrict__ y, const int* __restrict__ src,
    const int* __restrict__ dst, const int4* __restrict__ dst4, int E4,
    const float* __restrict__ emb, const float* __restrict__ W0,
    const float* __restrict__ as0, const float* __restrict__ ad0,
    const float* __restrict__ b0,  const float* __restrict__ W1,
    const float* __restrict__ as1, const float* __restrict__ ad1,
    const float* __restrict__ b1,  const float* __restrict__ pw1,
    const float* __restrict__ pb1, const float* __restrict__ pw2,
    const float* __restrict__ pb2, float* __restrict__ out,
    int N, int E, int V)
{
    __shared__ int    s_gen, s_tailf;
    __shared__ int    s_eidx[MAXDEG];
    __shared__ int    s_ecnt;
    __shared__ float  s_e[(MAXDEG + 1) * NH];          // softmax energies/alphas
    __shared__ __align__(16) float s_fs[FDIM];         // input vector for matvecs
    __shared__ __align__(16) float s_vec[FDIM];        // matvec output
    __shared__ float4 s_mv[4][64];                     // split-k partials
    __shared__ float  s_red[8][2];
    __shared__ float  s_snorm;

    const int tid  = threadIdx.x;
    const int bid  = blockIdx.x;
    const int wid  = tid >> 5, lane = tid & 31;
    const int nth  = GRID * TPB;
    const int gtid = bid * TPB + tid;

    // ======== P1: scan edges for dst == N-1 =================================
    {
        int tgt = N - 1;
        if (E4 > 0) {
            for (int i = gtid; i < E4; i += 4 * nth) {
                int ib = i + nth, ic = i + 2 * nth, id = i + 3 * nth;
                int4 A = dst4[i];
                int4 B = ib < E4 ? dst4[ib] : make_int4(-1,-1,-1,-1);
                int4 C = ic < E4 ? dst4[ic] : make_int4(-1,-1,-1,-1);
                int4 D = id < E4 ? dst4[id] : make_int4(-1,-1,-1,-1);
                s1_hit(A.x, tgt, src, 4*i);   s1_hit(A.y, tgt, src, 4*i+1);
                s1_hit(A.z, tgt, src, 4*i+2); s1_hit(A.w, tgt, src, 4*i+3);
                s1_hit(B.x, tgt, src, 4*ib);  s1_hit(B.y, tgt, src, 4*ib+1);
                s1_hit(B.z, tgt, src, 4*ib+2);s1_hit(B.w, tgt, src, 4*ib+3);
                s1_hit(C.x, tgt, src, 4*ic);  s1_hit(C.y, tgt, src, 4*ic+1);
                s1_hit(C.z, tgt, src, 4*ic+2);s1_hit(C.w, tgt, src, 4*ic+3);
                s1_hit(D.x, tgt, src, 4*id);  s1_hit(D.y, tgt, src, 4*id+1);
                s1_hit(D.z, tgt, src, 4*id+2);s1_hit(D.w, tgt, src, 4*id+3);
            }
            for (int e = 4 * E4 + gtid; e < E; e += nth) s1_hit(dst[e], tgt, src, e);
        } else {
            for (int e = gtid; e < E; e += nth) s1_hit(dst[e], tgt, src, e);
        }
    }
    GBAR({   // ---- prep1: claim 1-hop targets, build bitmap, resolve slots
        int n1 = min(VREAD(g_cnt[0]), MAXL1);
        if (tid == 0) {
            g_uslot[N - 1] = 1;
            g_ulist[0] = N - 1;
            g_cnt[2] = 1;
            atomicOr(&g_tbit[(N - 1) >> 5], 1u << ((N - 1) & 31));
        }
        __syncthreads();
        for (int i = tid; i < n1; i += TPB) {
            int s = g_l1_src[i];
            if (atomicCAS(&g_uslot[s], 0, -1) == 0) {
                int p = atomicAdd(&g_cnt[2], 1);
                g_uslot[s] = p + 1;
                if (p < MAXU) g_ulist[p] = s;
                atomicOr(&g_tbit[s >> 5], 1u << (s & 31));
            }
        }
        __syncthreads();
        if (tid == 0) g_cnt[1] = g_cnt[2];
        for (int i = tid; i < n1; i += TPB)
            g_l1_us[i] = g_uslot[g_l1_src[i]] - 1;
    });

    // ======== P2: scan edges for dst in target set ==========================
    {
        if (E4 > 0) {
            for (int i = gtid; i < E4; i += 4 * nth) {
                int ib = i + nth, ic = i + 2 * nth, id = i + 3 * nth;
                int4 A = dst4[i];
                int4 B = ib < E4 ? dst4[ib] : make_int4(-1,-1,-1,-1);
                int4 C = ic < E4 ? dst4[ic] : make_int4(-1,-1,-1,-1);
                int4 D = id < E4 ? dst4[id] : make_int4(-1,-1,-1,-1);
                s2_hit(A.x, N, src, 4*i);   s2_hit(A.y, N, src, 4*i+1);
                s2_hit(A.z, N, src, 4*i+2); s2_hit(A.w, N, src, 4*i+3);
                s2_hit(B.x, N, src, 4*ib);  s2_hit(B.y, N, src, 4*ib+1);
                s2_hit(B.z, N, src, 4*ib+2);s2_hit(B.w, N, src, 4*ib+3);
                s2_hit(C.x, N, src, 4*ic);  s2_hit(C.y, N, src, 4*ic+1);
                s2_hit(C.z, N, src, 4*ic+2);s2_hit(C.w, N, src, 4*ic+3);
                s2_hit(D.x, N, src, 4*id);  s2_hit(D.y, N, src, 4*id+1);
                s2_hit(D.z, N, src, 4*id+2);s2_hit(D.w, N, src, 4*id+3);
            }
            for (int e = 4 * E4 + gtid; e < E; e += nth) s2_hit(dst[e], N, src, e);
        } else {
            for (int e = gtid; e < E; e += nth) s2_hit(dst[e], N, src, e);
        }
    }
    GBAR({   // ---- prep2: claim 2-hop frontier, resolve e1 slots
        int n = min(VREAD(g_cnt[3]), MAXE1);
        for (int i = tid; i < n; i += TPB) {
            int s = g_e1_src[i];
            if (atomicCAS(&g_uslot[s], 0, -1) == 0) {
                int p = atomicAdd(&g_cnt[2], 1);
                g_uslot[s] = p + 1;
                if (p < MAXU) g_ulist[p] = s;
            }
        }
        __syncthreads();
        for (int i = tid; i < n; i += TPB) {
            g_e1_us[i]  = g_uslot[g_e1_src[i]] - 1;
            g_e1_dst[i] = g_uslot[g_e1_dstn[i]] - 1;
        }
    });

    // ======== P3: h0 = emb[y]@W0 (+ al0), CTA per frontier node =============
    {
        int ucnt = min(VREAD(g_cnt[2]), MAXU);
        const float4* W04 = (const float4*)W0;      // [DIN][64]
        int cg = tid & 63, kq = tid >> 6;
        for (int u = bid; u < ucnt; u += GRID) {
            int node = g_ulist[u];
            if (tid < DIN / 4)
                ((float4*)s_fs)[tid] = ((const float4*)(emb + (long long)y[node] * DIN))[tid];
            __syncthreads();
            float4 a = make_float4(0.f, 0.f, 0.f, 0.f);
            #pragma unroll
            for (int k = kq * 16; k < kq * 16 + 16; k++) {
                float x = s_fs[k];
                float4 w = W04[k * 64 + cg];
                a.x += x * w.x; a.y += x * w.y; a.z += x * w.z; a.w += x * w.w;
            }
            s_mv[kq][cg] = a;
            __syncthreads();
            if (tid < 64) {
                float4 r0 = s_mv[0][tid], r1 = s_mv[1][tid];
                float4 r2 = s_mv[2][tid], r3 = s_mv[3][tid];
                float4 r = make_float4(r0.x+r1.x+r2.x+r3.x, r0.y+r1.y+r2.y+r3.y,
                                       r0.z+r1.z+r2.z+r3.z, r0.w+r1.w+r2.w+r3.w);
                ((float4*)s_vec)[tid] = r;
                ((float4*)(g_h0[u]))[tid] = r;
            }
            __syncthreads();
            float hv = s_vec[tid];
            float ps = warp_sum(hv * as0[tid]);
            float pd = warp_sum(hv * ad0[tid]);
            if (lane == 0) { s_red[wid][0] = ps; s_red[wid][1] = pd; }
            __syncthreads();
            if (tid < 2 * NH) {
                int h = tid & 3;
                g_al0[u][tid] = (tid < NH) ? (s_red[2*h][0] + s_red[2*h+1][0])
                                           : (s_red[2*h][1] + s_red[2*h+1][1]);
            }
            __syncthreads();
        }
    }
    GBAR({});

    // ======== P4: layer-0 agg + layer-1 transform (CTA t < tcnt) ============
    {
        int tcnt = VREAD(g_cnt[1]);
        int e1n  = min(VREAD(g_cnt[3]), MAXE1);
        if (bid < tcnt) {
            int t = bid;
            if (tid == 0) s_ecnt = 0;
            __syncthreads();
            for (int i = tid; i < e1n; i += TPB)
                if (g_e1_dst[i] == t) {
                    int p = atomicAdd(&s_ecnt, 1);
                    if (p < MAXDEG) s_eidx[p] = g_e1_us[i];
                }
            __syncthreads();
            int ne = min(s_ecnt, MAXDEG);       // +1 implicit self-loop

            float ald0 = g_al0[t][NH + 0], ald1 = g_al0[t][NH + 1];
            float ald2 = g_al0[t][NH + 2], ald3 = g_al0[t][NH + 3];
            for (int idx = tid; idx < (ne + 1) * NH; idx += TPB) {
                int i = idx >> 2, h = idx & 3;
                int us = (i == ne) ? t : s_eidx[i];
                float ad = (h == 0) ? ald0 : (h == 1) ? ald1 : (h == 2) ? ald2 : ald3;
                s_e[idx] = lrelu(g_al0[us][h] + ad);
            }
            __syncthreads();
            if (wid < NH) {       // warp per head: max, exp, normalize
                int h = wid;
                float m = -3.0e38f;
                for (int i = lane; i <= ne; i += 32) m = fmaxf(m, s_e[i*4 + h]);
                m = warp_max(m);
                float d = 0.f;
                for (int i = lane; i <= ne; i += 32) {
                    float ev = expf(s_e[i*4 + h] - m);
                    s_e[i*4 + h] = ev;
                    d += ev;
                }
                d = warp_sum(d) + 1e-16f;
                float inv = 1.f / d;
                for (int i = lane; i <= ne; i += 32) s_e[i*4 + h] *= inv;
            }
            __syncthreads();

            // weighted feature sum (2 accumulators for load ILP) + ELU + norm
            int c = tid, head = c >> 6;
            float acc = 0.f, acc2 = 0.f;
            {
                int i = 0;
                for (; i + 1 < ne; i += 2) {
                    int us0 = s_eidx[i], us1 = s_eidx[i + 1];
                    acc  += s_e[i*4 + head]       * g_h0[us0][c];
                    acc2 += s_e[(i + 1)*4 + head] * g_h0[us1][c];
                }
                for (; i < ne; i++)
                    acc += s_e[i*4 + head] * g_h0[s_eidx[i]][c];
                acc += s_e[ne*4 + head] * g_h0[t][c];   // self loop
                acc += acc2;
            }
            acc += b0[c];
            acc = acc > 0.f ? acc : expm1f(acc);
            float ss = warp_sum(acc * acc);
            if (lane == 0) s_red[wid][0] = ss;
            __syncthreads();
            if (tid == 0) {
                float s = 0.f;
                for (int w = 0; w < 8; w++) s += s_red[w][0];
                s_snorm = fmaxf(sqrtf(s), 1e-12f);
            }
            __syncthreads();
            s_fs[c] = acc / s_snorm;
            __syncthreads();

            // h1 = fs @ W1 (split-k float4) + al1
            {
                const float4* W14 = (const float4*)W1;  // [256][64]
                int cg = tid & 63, kq = tid >> 6;
                float4 a = make_float4(0.f, 0.f, 0.f, 0.f);
                #pragma unroll 16
                for (int k = kq * 64; k < kq * 64 + 64; k++) {
                    float x = s_fs[k];
                    float4 w = W14[k * 64 + cg];
                    a.x += x * w.x; a.y += x * w.y; a.z += x * w.z; a.w += x * w.w;
                }
                s_mv[kq][cg] = a;
                __syncthreads();
                if (tid < 64) {
                    float4 r0 = s_mv[0][tid], r1 = s_mv[1][tid];
                    float4 r2 = s_mv[2][tid], r3 = s_mv[3][tid];
                    float4 r = make_float4(r0.x+r1.x+r2.x+r3.x, r0.y+r1.y+r2.y+r3.y,
                                           r0.z+r1.z+r2.z+r3.z, r0.w+r1.w+r2.w+r3.w);
                    ((float4*)s_vec)[tid] = r;
                    ((float4*)(g_h1[t]))[tid] = r;
                }
                __syncthreads();
                float hv = s_vec[tid];
                float ps = warp_sum(hv * as1[tid]);
                float pd = warp_sum(hv * ad1[tid]);
                if (lane == 0) { s_red[wid][0] = ps; s_red[wid][1] = pd; }
                __syncthreads();
                if (tid < 2 * NH) {
                    int h = tid & 3;
                    g_al1[t][tid] = (tid < NH) ? (s_red[2*h][0] + s_red[2*h+1][0])
                                               : (s_red[2*h][1] + s_red[2*h+1][1]);
                }
            }
        }
    }
    GBAR({   // ---- final: layer-1 aggregation at N-1 + ctx MLP
        int n1 = min(VREAD(g_cnt[0]), MAXDEG);

        float ald0 = g_al1[0][NH + 0], ald1 = g_al1[0][NH + 1];
        float ald2 = g_al1[0][NH + 2], ald3 = g_al1[0][NH + 3];
        for (int idx = tid; idx < (n1 + 1) * NH; idx += TPB) {
            int i = idx >> 2, h = idx & 3;
            int us = (i == n1) ? 0 : g_l1_us[i];
            float ad = (h == 0) ? ald0 : (h == 1) ? ald1 : (h == 2) ? ald2 : ald3;
            s_e[idx] = lrelu(g_al1[us][h] + ad);
        }
        __syncthreads();
        if (wid < NH) {
            int h = wid;
            float m = -3.0e38f;
            for (int i = lane; i <= n1; i += 32) m = fmaxf(m, s_e[i*4 + h]);
            m = warp_max(m);
            float d = 0.f;
            for (int i = lane; i <= n1; i += 32) {
                float ev = expf(s_e[i*4 + h] - m);
                s_e[i*4 + h] = ev;
                d += ev;
            }
            d = warp_sum(d) + 1e-16f;
            float inv = 1.f / d;
            for (int i = lane; i <= n1; i += 32) s_e[i*4 + h] *= inv;
        }
        __syncthreads();

        int c = tid, head = c >> 6;
        float acc = 0.f, acc2 = 0.f;
        {
            int i = 0;
            for (; i + 1 < n1; i += 2) {
                int us0 = g_l1_us[i], us1 = g_l1_us[i + 1];
                acc  += s_e[i*4 + head]       * g_h1[us0][c];
                acc2 += s_e[(i + 1)*4 + head] * g_h1[us1][c];
            }
            for (; i < n1; i++)
                acc += s_e[i*4 + head] * g_h1[g_l1_us[i]][c];
            acc += s_e[n1*4 + head] * g_h1[0][c];     // self loop (slot 0 = N-1)
            acc += acc2;
        }
        acc += b1[c];
        acc = acc > 0.f ? acc : expm1f(acc);
        float ss = warp_sum(acc * acc);
        if (lane == 0) s_red[wid][0] = ss;
        __syncthreads();
        if (tid == 0) {
            float s = 0.f;
            for (int w = 0; w < 8; w++) s += s_red[w][0];
            s_snorm = fmaxf(sqrtf(s), 1e-12f);
        }
        __syncthreads();
        s_fs[c] = acc / s_snorm;
        __syncthreads();

        // mlp = relu(ctx @ pw1 + pb1): thread = (col, k-quarter), k 64 each
        {
            int col = tid & 63, kq = tid >> 6;
            float a = 0.f;
            #pragma unroll 16
            for (int k = kq * 64; k < kq * 64 + 64; k++)
                a += s_fs[k] * pw1[k * DIN + col];
            s_mv[kq][col].x = a;
            __syncthreads();
            if (tid < DIN) {
                float v = pb1[tid] + s_mv[0][tid].x + s_mv[1][tid].x
                                   + s_mv[2][tid].x + s_mv[3][tid].x;
                g_mlp[tid] = fmaxf(v, 0.f);
            }
        }
    });

    // ======== P5: out = mlp @ pw2 + pb2 (+ cleanup by last CTA) =============
    {
        if (bid == GRID - 1) {
            int ucnt = min(VREAD(g_cnt[2]), MAXU);
            int tcnt = VREAD(g_cnt[1]);
            for (int i = tid; i < ucnt; i += TPB) {
                int node = g_ulist[i];
                g_uslot[node] = 0;
                if (i < tcnt) atomicAnd(&g_tbit[node >> 5], ~(1u << (node & 31)));
            }
            __syncthreads();
            if (tid == 0) {
                g_cnt[0] = 0; g_cnt[1] = 0; g_cnt[2] = 0; g_cnt[3] = 0;
                __threadfence();
            }
        }

        if (tid < DIN) s_fs[tid] = g_mlp[tid];
        __syncthreads();

        if ((V & 3) == 0) {
            int V4 = V >> 2;
            const float4* pw24 = (const float4*)pw2;
            const float4* pb24 = (const float4*)pb2;
            float4* out4 = (float4*)out;
            int chunk = (V4 + GRID - 1) / GRID;
            int lo = bid * chunk;
            int hi = min(lo + chunk, V4);
            for (int v = lo + tid; v < hi; v += TPB) {
                float4 acc = pb24[v];
                #pragma unroll 16
                for (int j = 0; j < DIN; j++) {
                    float w = s_fs[j];
                    float4 p = pw24[(size_t)j * V4 + v];
                    acc.x += w * p.x; acc.y += w * p.y;
                    acc.z += w * p.z; acc.w += w * p.w;
                }
                out4[v] = acc;
            }
        } else {
            int chunk = (V + GRID - 1) / GRID;
            int lo = bid * chunk;
            int hi = min(lo + chunk, V);
            for (int v = lo + tid; v < hi; v += TPB) {
                float acc = pb2[v];
                for (int j = 0; j < DIN; j++) acc += s_fs[j] * pw2[(size_t)j * V + v];
                out[v] = acc;
            }
        }
    }
}

// ---------------- launcher ---------------------------------------------------
extern "C" void kernel_launch(void* const* d_in, const int* in_sizes, int n_in,
                              void* d_out, int out_size) {
    const int*   y   = (const int*)  d_in[0];
    const int*   ei  = (const int*)  d_in[1];
    const float* emb = (const float*)d_in[2];
    const float* W0  = (const float*)d_in[3];
    const float* as0 = (const float*)d_in[4];
    const float* ad0 = (const float*)d_in[5];
    const float* b0  = (const float*)d_in[6];
    const float* W1  = (const float*)d_in[7];
    const float* as1 = (const float*)d_in[8];
    const float* ad1 = (const float*)d_in[9];
    const float* b1  = (const float*)d_in[10];
    const float* pw1 = (const float*)d_in[11];
    const float* pb1 = (const float*)d_in[12];
    const float* pw2 = (const float*)d_in[13];
    const float* pb2 = (const float*)d_in[14];
    float* out = (float*)d_out;

    int N = in_sizes[0];
    int E = in_sizes[1] / 2;
    int V = out_size;
    const int* srcp = ei;
    const int* dstp = ei + E;
    int E4 = (((size_t)dstp & 15) == 0) ? (E >> 2) : 0;
    const int4* dst4 = (const int4*)dstp;

    mega<<<GRID, TPB>>>(y, srcp, dstp, dst4, E4,
                        emb, W0, as0, ad0, b0, W1, as1, ad1, b1,
                        pw1, pb1, pw2, pb2, out, N, E, V);
}

// round 13
// speedup vs baseline: 1.4094x; 1.4094x over previous
#include <cuda_runtime.h>
#include <math.h>

#define DIN    64
#define FDIM   256
#define NH     4
#define NMAXC  50000
#define MAXL1  4096
#define MAXT   (MAXL1 + 1)
#define MAXE1  32768
#define MAXU   (MAXT + MAXE1)
#define MAXDEG 512
#define NBW    1568
#define GRID   148
#define TPB    256

#define VREAD(x) (*(volatile int*)&(x))

// ---------------- scratch (static device globals, zero-initialized) ---------
__device__ int      g_uslot[NMAXC];     // 0=free, -1=pending, k+1 = slot k
__device__ unsigned g_tbit[NBW];
__device__ int      g_l1_src[MAXL1];
__device__ int      g_l1_us[MAXL1];
__device__ int      g_e1_dstn[MAXE1];
__device__ int      g_e1_dst[MAXE1];
__device__ int      g_e1_src[MAXE1];
__device__ int      g_e1_us[MAXE1];
__device__ int      g_ulist[MAXU];
__device__ int      g_cnt[4];           // 0=l1 1=tgt 2=u 3=e1 (self-cleaned)
__device__ __align__(16) float g_h0[MAXU][FDIM];
__device__ float    g_al0[MAXU][2*NH];
__device__ __align__(16) float g_h1[MAXT][FDIM];
__device__ float    g_al1[MAXT][2*NH];
__device__ float    g_mlp[DIN];
__device__ int      g_barc;             // barrier arrive counter (self-resets)
__device__ int      g_barg;             // barrier generation (monotonic)

// ---------------- helpers ---------------------------------------------------
__device__ __forceinline__ float warp_sum(float v) {
    #pragma unroll
    for (int o = 16; o; o >>= 1) v += __shfl_xor_sync(0xffffffffu, v, o);
    return v;
}
__device__ __forceinline__ float warp_max(float v) {
    #pragma unroll
    for (int o = 16; o; o >>= 1) v = fmaxf(v, __shfl_xor_sync(0xffffffffu, v, o));
    return v;
}
__device__ __forceinline__ float lrelu(float x) { return x > 0.f ? x : 0.2f * x; }

__device__ __forceinline__ void s1_hit(int d, int tgt, const int* __restrict__ src, int e) {
    if (d == tgt) {
        int p = atomicAdd(&g_cnt[0], 1);
        if (p < MAXL1) g_l1_src[p] = src[e];
    }
}
__device__ __forceinline__ void s2_hit(int d, int N, const int* __restrict__ src, int e) {
    if ((unsigned)d < (unsigned)N) {
        if ((g_tbit[d >> 5] >> (d & 31)) & 1u) {
            int p = atomicAdd(&g_cnt[3], 1);
            if (p < MAXE1) { g_e1_dstn[p] = d; g_e1_src[p] = src[e]; }
        }
    }
}

// Grid barrier: last-arriving CTA runs TAILCODE (block-parallel) before release.
#define GBAR(...) do {                                                         \
    __syncthreads();                                                           \
    if (threadIdx.x == 0) {                                                    \
        __threadfence();                                                       \
        s_gen  = VREAD(g_barg);                                                \
        s_tailf = (atomicAdd(&g_barc, 1) == GRID - 1);                         \
        if (s_tailf) __threadfence();                                          \
    }                                                                          \
    __syncthreads();                                                           \
    if (s_tailf) {                                                             \
        { __VA_ARGS__ }                                                        \
        __syncthreads();                                                       \
        if (threadIdx.x == 0) {                                                \
            g_barc = 0;                                                        \
            __threadfence();                                                   \
            *(volatile int*)&g_barg = s_gen + 1;                               \
        }                                                                      \
        __syncthreads();                                                       \
    } else {                                                                   \
        if (threadIdx.x == 0) {                                                \
            while (VREAD(g_barg) == s_gen) __nanosleep(32);                    \
            __threadfence();                                                   \
        }                                                                      \
        __syncthreads();                                                       \
    }                                                                          \
} while (0)

// ---------------- the megakernel --------------------------------------------
__global__ void __launch_bounds__(TPB) mega(
    const int* __restrict__ y, const int* __restrict__ src,
    const int* __restrict__ dst, const int4* __restrict__ dst4, int E4,
    const float* __restrict__ emb, const float* __restrict__ W0,
    const float* __restrict__ as0, const float* __restrict__ ad0,
    const float* __restrict__ b0,  const float* __restrict__ W1,
    const float* __restrict__ as1, const float* __restrict__ ad1,
    const float* __restrict__ b1,  const float* __restrict__ pw1,
    const float* __restrict__ pb1, const float* __restrict__ pw2,
    const float* __restrict__ pb2, float* __restrict__ out,
    int N, int E, int V)
{
    __shared__ int    s_gen, s_tailf;
    __shared__ int    s_eidx[MAXDEG];
    __shared__ int    s_ecnt;
    __shared__ float  s_e[(MAXDEG + 1) * NH];          // softmax energies/alphas
    __shared__ __align__(16) float s_fs[FDIM];         // input vector for matvecs
    __shared__ __align__(16) float s_vec[FDIM];        // matvec output
    __shared__ float4 s_mv[4][64];                     // split-k partials
    __shared__ float  s_red[8][2];
    __shared__ float  s_snorm;

    const int tid  = threadIdx.x;
    const int bid  = blockIdx.x;
    const int wid  = tid >> 5, lane = tid & 31;
    const int nth  = GRID * TPB;
    const int gtid = bid * TPB + tid;

    // ======== P1: scan edges for dst == N-1 =================================
    {
        int tgt = N - 1;
        if (E4 > 0) {
            for (int i = gtid; i < E4; i += 4 * nth) {
                int ib = i + nth, ic = i + 2 * nth, id = i + 3 * nth;
                int4 A = dst4[i];
                int4 B = ib < E4 ? dst4[ib] : make_int4(-1,-1,-1,-1);
                int4 C = ic < E4 ? dst4[ic] : make_int4(-1,-1,-1,-1);
                int4 D = id < E4 ? dst4[id] : make_int4(-1,-1,-1,-1);
                s1_hit(A.x, tgt, src, 4*i);   s1_hit(A.y, tgt, src, 4*i+1);
                s1_hit(A.z, tgt, src, 4*i+2); s1_hit(A.w, tgt, src, 4*i+3);
                s1_hit(B.x, tgt, src, 4*ib);  s1_hit(B.y, tgt, src, 4*ib+1);
                s1_hit(B.z, tgt, src, 4*ib+2);s1_hit(B.w, tgt, src, 4*ib+3);
                s1_hit(C.x, tgt, src, 4*ic);  s1_hit(C.y, tgt, src, 4*ic+1);
                s1_hit(C.z, tgt, src, 4*ic+2);s1_hit(C.w, tgt, src, 4*ic+3);
                s1_hit(D.x, tgt, src, 4*id);  s1_hit(D.y, tgt, src, 4*id+1);
                s1_hit(D.z, tgt, src, 4*id+2);s1_hit(D.w, tgt, src, 4*id+3);
            }
            for (int e = 4 * E4 + gtid; e < E; e += nth) s1_hit(dst[e], tgt, src, e);
        } else {
            for (int e = gtid; e < E; e += nth) s1_hit(dst[e], tgt, src, e);
        }
    }
    GBAR({   // ---- prep1: claim 1-hop targets, build bitmap, resolve slots
        int n1 = min(VREAD(g_cnt[0]), MAXL1);
        if (tid == 0) {
            g_uslot[N - 1] = 1;
            g_ulist[0] = N - 1;
            g_cnt[2] = 1;
            atomicOr(&g_tbit[(N - 1) >> 5], 1u << ((N - 1) & 31));
        }
        __syncthreads();
        for (int i = tid; i < n1; i += TPB) {
            int s = g_l1_src[i];
            if (atomicCAS(&g_uslot[s], 0, -1) == 0) {
                int p = atomicAdd(&g_cnt[2], 1);
                g_uslot[s] = p + 1;
                if (p < MAXU) g_ulist[p] = s;
                atomicOr(&g_tbit[s >> 5], 1u << (s & 31));
            }
        }
        __syncthreads();
        if (tid == 0) g_cnt[1] = g_cnt[2];
        for (int i = tid; i < n1; i += TPB)
            g_l1_us[i] = g_uslot[g_l1_src[i]] - 1;
    });

    // ======== P2: scan edges for dst in target set ==========================
    {
        if (E4 > 0) {
            for (int i = gtid; i < E4; i += 4 * nth) {
                int ib = i + nth, ic = i + 2 * nth, id = i + 3 * nth;
                int4 A = dst4[i];
                int4 B = ib < E4 ? dst4[ib] : make_int4(-1,-1,-1,-1);
                int4 C = ic < E4 ? dst4[ic] : make_int4(-1,-1,-1,-1);
                int4 D = id < E4 ? dst4[id] : make_int4(-1,-1,-1,-1);
                s2_hit(A.x, N, src, 4*i);   s2_hit(A.y, N, src, 4*i+1);
                s2_hit(A.z, N, src, 4*i+2); s2_hit(A.w, N, src, 4*i+3);
                s2_hit(B.x, N, src, 4*ib);  s2_hit(B.y, N, src, 4*ib+1);
                s2_hit(B.z, N, src, 4*ib+2);s2_hit(B.w, N, src, 4*ib+3);
                s2_hit(C.x, N, src, 4*ic);  s2_hit(C.y, N, src, 4*ic+1);
                s2_hit(C.z, N, src, 4*ic+2);s2_hit(C.w, N, src, 4*ic+3);
                s2_hit(D.x, N, src, 4*id);  s2_hit(D.y, N, src, 4*id+1);
                s2_hit(D.z, N, src, 4*id+2);s2_hit(D.w, N, src, 4*id+3);
            }
            for (int e = 4 * E4 + gtid; e < E; e += nth) s2_hit(dst[e], N, src, e);
        } else {
            for (int e = gtid; e < E; e += nth) s2_hit(dst[e], N, src, e);
        }
    }
    GBAR({   // ---- prep2: claim 2-hop frontier, resolve e1 slots
        int n = min(VREAD(g_cnt[3]), MAXE1);
        for (int i = tid; i < n; i += TPB) {
            int s = g_e1_src[i];
            if (atomicCAS(&g_uslot[s], 0, -1) == 0) {
                int p = atomicAdd(&g_cnt[2], 1);
                g_uslot[s] = p + 1;
                if (p < MAXU) g_ulist[p] = s;
            }
        }
        __syncthreads();
        for (int i = tid; i < n; i += TPB) {
            g_e1_us[i]  = g_uslot[g_e1_src[i]] - 1;
            g_e1_dst[i] = g_uslot[g_e1_dstn[i]] - 1;
        }
    });

    // ======== P3: h0 = emb[y]@W0 (+ al0), CTA per frontier node =============
    {
        int ucnt = min(VREAD(g_cnt[2]), MAXU);
        const float4* W04 = (const float4*)W0;      // [DIN][64]
        int cg = tid & 63, kq = tid >> 6;
        for (int u = bid; u < ucnt; u += GRID) {
            int node = g_ulist[u];
            if (tid < DIN / 4)
                ((float4*)s_fs)[tid] = ((const float4*)(emb + (long long)y[node] * DIN))[tid];
            __syncthreads();
            float4 a = make_float4(0.f, 0.f, 0.f, 0.f);
            #pragma unroll
            for (int k = kq * 16; k < kq * 16 + 16; k++) {
                float x = s_fs[k];
                float4 w = W04[k * 64 + cg];
                a.x += x * w.x; a.y += x * w.y; a.z += x * w.z; a.w += x * w.w;
            }
            s_mv[kq][cg] = a;
            __syncthreads();
            if (tid < 64) {
                float4 r0 = s_mv[0][tid], r1 = s_mv[1][tid];
                float4 r2 = s_mv[2][tid], r3 = s_mv[3][tid];
                float4 r = make_float4(r0.x+r1.x+r2.x+r3.x, r0.y+r1.y+r2.y+r3.y,
                                       r0.z+r1.z+r2.z+r3.z, r0.w+r1.w+r2.w+r3.w);
                ((float4*)s_vec)[tid] = r;
                ((float4*)(g_h0[u]))[tid] = r;
            }
            __syncthreads();
            float hv = s_vec[tid];
            float ps = warp_sum(hv * as0[tid]);
            float pd = warp_sum(hv * ad0[tid]);
            if (lane == 0) { s_red[wid][0] = ps; s_red[wid][1] = pd; }
            __syncthreads();
            if (tid < 2 * NH) {
                int h = tid & 3;
                g_al0[u][tid] = (tid < NH) ? (s_red[2*h][0] + s_red[2*h+1][0])
                                           : (s_red[2*h][1] + s_red[2*h+1][1]);
            }
            __syncthreads();
        }
    }
    GBAR({});

    // ======== P4: layer-0 agg + layer-1 transform (CTA t < tcnt) ============
    {
        int tcnt = VREAD(g_cnt[1]);
        int e1n  = min(VREAD(g_cnt[3]), MAXE1);
        if (bid < tcnt) {
            int t = bid;
            if (tid == 0) s_ecnt = 0;
            __syncthreads();
            for (int i = tid; i < e1n; i += TPB)
                if (g_e1_dst[i] == t) {
                    int p = atomicAdd(&s_ecnt, 1);
                    if (p < MAXDEG) s_eidx[p] = g_e1_us[i];
                }
            __syncthreads();
            int ne = min(s_ecnt, MAXDEG);       // +1 implicit self-loop

            float ald0 = g_al0[t][NH + 0], ald1 = g_al0[t][NH + 1];
            float ald2 = g_al0[t][NH + 2], ald3 = g_al0[t][NH + 3];
            for (int idx = tid; idx < (ne + 1) * NH; idx += TPB) {
                int i = idx >> 2, h = idx & 3;
                int us = (i == ne) ? t : s_eidx[i];
                float ad = (h == 0) ? ald0 : (h == 1) ? ald1 : (h == 2) ? ald2 : ald3;
                s_e[idx] = lrelu(g_al0[us][h] + ad);
            }
            __syncthreads();
            if (wid < NH) {       // warp per head: max, exp, normalize
                int h = wid;
                float m = -3.0e38f;
                for (int i = lane; i <= ne; i += 32) m = fmaxf(m, s_e[i*4 + h]);
                m = warp_max(m);
                float d = 0.f;
                for (int i = lane; i <= ne; i += 32) {
                    float ev = expf(s_e[i*4 + h] - m);
                    s_e[i*4 + h] = ev;
                    d += ev;
                }
                d = warp_sum(d) + 1e-16f;
                float inv = 1.f / d;
                for (int i = lane; i <= ne; i += 32) s_e[i*4 + h] *= inv;
            }
            __syncthreads();

            // weighted feature sum (2 accumulators for load ILP) + ELU + norm
            int c = tid, head = c >> 6;
            float acc = 0.f, acc2 = 0.f;
            {
                int i = 0;
                for (; i + 1 < ne; i += 2) {
                    int us0 = s_eidx[i], us1 = s_eidx[i + 1];
                    acc  += s_e[i*4 + head]       * g_h0[us0][c];
                    acc2 += s_e[(i + 1)*4 + head] * g_h0[us1][c];
                }
                for (; i < ne; i++)
                    acc += s_e[i*4 + head] * g_h0[s_eidx[i]][c];
                acc += s_e[ne*4 + head] * g_h0[t][c];   // self loop
                acc += acc2;
            }
            acc += b0[c];
            acc = acc > 0.f ? acc : expm1f(acc);
            float ss = warp_sum(acc * acc);
            if (lane == 0) s_red[wid][0] = ss;
            __syncthreads();
            if (tid == 0) {
                float s = 0.f;
                for (int w = 0; w < 8; w++) s += s_red[w][0];
                s_snorm = fmaxf(sqrtf(s), 1e-12f);
            }
            __syncthreads();
            s_fs[c] = acc / s_snorm;
            __syncthreads();

            // h1 = fs @ W1 (split-k float4) + al1
            {
                const float4* W14 = (const float4*)W1;  // [256][64]
                int cg = tid & 63, kq = tid >> 6;
                float4 a = make_float4(0.f, 0.f, 0.f, 0.f);
                #pragma unroll 16
                for (int k = kq * 64; k < kq * 64 + 64; k++) {
                    float x = s_fs[k];
                    float4 w = W14[k * 64 + cg];
                    a.x += x * w.x; a.y += x * w.y; a.z += x * w.z; a.w += x * w.w;
                }
                s_mv[kq][cg] = a;
                __syncthreads();
                if (tid < 64) {
                    float4 r0 = s_mv[0][tid], r1 = s_mv[1][tid];
                    float4 r2 = s_mv[2][tid], r3 = s_mv[3][tid];
                    float4 r = make_float4(r0.x+r1.x+r2.x+r3.x, r0.y+r1.y+r2.y+r3.y,
                                           r0.z+r1.z+r2.z+r3.z, r0.w+r1.w+r2.w+r3.w);
                    ((float4*)s_vec)[tid] = r;
                    ((float4*)(g_h1[t]))[tid] = r;
                }
                __syncthreads();
                float hv = s_vec[tid];
                float ps = warp_sum(hv * as1[tid]);
                float pd = warp_sum(hv * ad1[tid]);
                if (lane == 0) { s_red[wid][0] = ps; s_red[wid][1] = pd; }
                __syncthreads();
                if (tid < 2 * NH) {
                    int h = tid & 3;
                    g_al1[t][tid] = (tid < NH) ? (s_red[2*h][0] + s_red[2*h+1][0])
                                               : (s_red[2*h][1] + s_red[2*h+1][1]);
                }
            }
        }
    }
    GBAR({   // ---- final: layer-1 aggregation at N-1 + ctx MLP
        int n1 = min(VREAD(g_cnt[0]), MAXDEG);

        float ald0 = g_al1[0][NH + 0], ald1 = g_al1[0][NH + 1];
        float ald2 = g_al1[0][NH + 2], ald3 = g_al1[0][NH + 3];
        for (int idx = tid; idx < (n1 + 1) * NH; idx += TPB) {
            int i = idx >> 2, h = idx & 3;
            int us = (i == n1) ? 0 : g_l1_us[i];
            float ad = (h == 0) ? ald0 : (h == 1) ? ald1 : (h == 2) ? ald2 : ald3;
            s_e[idx] = lrelu(g_al1[us][h] + ad);
        }
        __syncthreads();
        if (wid < NH) {
            int h = wid;
            float m = -3.0e38f;
            for (int i = lane; i <= n1; i += 32) m = fmaxf(m, s_e[i*4 + h]);
            m = warp_max(m);
            float d = 0.f;
            for (int i = lane; i <= n1; i += 32) {
                float ev = expf(s_e[i*4 + h] - m);
                s_e[i*4 + h] = ev;
                d += ev;
            }
            d = warp_sum(d) + 1e-16f;
            float inv = 1.f / d;
            for (int i = lane; i <= n1; i += 32) s_e[i*4 + h] *= inv;
        }
        __syncthreads();

        int c = tid, head = c >> 6;
        float acc = 0.f, acc2 = 0.f;
        {
            int i = 0;
            for (; i + 1 < n1; i += 2) {
                int us0 = g_l1_us[i], us1 = g_l1_us[i + 1];
                acc  += s_e[i*4 + head]       * g_h1[us0][c];
                acc2 += s_e[(i + 1)*4 + head] * g_h1[us1][c];
            }
            for (; i < n1; i++)
                acc += s_e[i*4 + head] * g_h1[g_l1_us[i]][c];
            acc += s_e[n1*4 + head] * g_h1[0][c];     // self loop (slot 0 = N-1)
            acc += acc2;
        }
        acc += b1[c];
        acc = acc > 0.f ? acc : expm1f(acc);
        float ss = warp_sum(acc * acc);
        if (lane == 0) s_red[wid][0] = ss;
        __syncthreads();
        if (tid == 0) {
            float s = 0.f;
            for (int w = 0; w < 8; w++) s += s_red[w][0];
            s_snorm = fmaxf(sqrtf(s), 1e-12f);
        }
        __syncthreads();
        s_fs[c] = acc / s_snorm;
        __syncthreads();

        // mlp = relu(ctx @ pw1 + pb1): thread = (col, k-quarter), k 64 each
        {
            int col = tid & 63, kq = tid >> 6;
            float a = 0.f;
            #pragma unroll 16
            for (int k = kq * 64; k < kq * 64 + 64; k++)
                a += s_fs[k] * pw1[k * DIN + col];
            s_mv[kq][col].x = a;
            __syncthreads();
            if (tid < DIN) {
                float v = pb1[tid] + s_mv[0][tid].x + s_mv[1][tid].x
                                   + s_mv[2][tid].x + s_mv[3][tid].x;
                g_mlp[tid] = fmaxf(v, 0.f);
            }
        }
    });

    // ======== P5: out = mlp @ pw2 + pb2 (+ cleanup by last CTA) =============
    {
        if (bid == GRID - 1) {
            int ucnt = min(VREAD(g_cnt[2]), MAXU);
            int tcnt = VREAD(g_cnt[1]);
            for (int i = tid; i < ucnt; i += TPB) {
                int node = g_ulist[i];
                g_uslot[node] = 0;
                if (i < tcnt) atomicAnd(&g_tbit[node >> 5], ~(1u << (node & 31)));
            }
            __syncthreads();
            if (tid == 0) {
                g_cnt[0] = 0; g_cnt[1] = 0; g_cnt[2] = 0; g_cnt[3] = 0;
                __threadfence();
            }
        }

        if (tid < DIN) s_fs[tid] = g_mlp[tid];
        __syncthreads();

        if ((V & 3) == 0) {
            int V4 = V >> 2;
            const float4* pw24 = (const float4*)pw2;
            const float4* pb24 = (const float4*)pb2;
            float4* out4 = (float4*)out;
            int chunk = (V4 + GRID - 1) / GRID;
            int lo = bid * chunk;
            int hi = min(lo + chunk, V4);
            for (int v = lo + tid; v < hi; v += TPB) {
                float4 acc = pb24[v];
                #pragma unroll 16
                for (int j = 0; j < DIN; j++) {
                    float w = s_fs[j];
                    float4 p = pw24[(size_t)j * V4 + v];
                    acc.x += w * p.x; acc.y += w * p.y;
                    acc.z += w * p.z; acc.w += w * p.w;
                }
                out4[v] = acc;
            }
        } else {
            int chunk = (V + GRID - 1) / GRID;
            int lo = bid * chunk;
            int hi = min(lo + chunk, V);
            for (int v = lo + tid; v < hi; v += TPB) {
                float acc = pb2[v];
                for (int j = 0; j < DIN; j++) acc += s_fs[j] * pw2[(size_t)j * V + v];
                out[v] = acc;
            }
        }
    }
}

// ---------------- launcher ---------------------------------------------------
extern "C" void kernel_launch(void* const* d_in, const int* in_sizes, int n_in,
                              void* d_out, int out_size) {
    const int*   y   = (const int*)  d_in[0];
    const int*   ei  = (const int*)  d_in[1];
    const float* emb = (const float*)d_in[2];
    const float* W0  = (const float*)d_in[3];
    const float* as0 = (const float*)d_in[4];
    const float* ad0 = (const float*)d_in[5];
    const float* b0  = (const float*)d_in[6];
    const float* W1  = (const float*)d_in[7];
    const float* as1 = (const float*)d_in[8];
    const float* ad1 = (const float*)d_in[9];
    const float* b1  = (const float*)d_in[10];
    const float* pw1 = (const float*)d_in[11];
    const float* pb1 = (const float*)d_in[12];
    const float* pw2 = (const float*)d_in[13];
    const float* pb2 = (const float*)d_in[14];
    float* out = (float*)d_out;

    int N = in_sizes[0];
    int E = in_sizes[1] / 2;
    int V = out_size;
    const int* srcp = ei;
    const int* dstp = ei + E;
    int E4 = (((size_t)dstp & 15) == 0) ? (E >> 2) : 0;
    const int4* dst4 = (const int4*)dstp;

    mega<<<GRID, TPB>>>(y, srcp, dstp, dst4, E4,
                        emb, W0, as0, ad0, b0, W1, as1, ad1, b1,
                        pw1, pb1, pw2, pb2, out, N, E, V);
}

// round 15
// speedup vs baseline: 1.5486x; 1.0988x over previous
#include <cuda_runtime.h>
#include <math.h>

#define DIN    64
#define FDIM   256
#define NH     4
#define NMAXC  50000
#define MAXL1  4096
#define MAXT   (MAXL1 + 1)
#define MAXE1  32768
#define MAXU   (MAXT + MAXE1)
#define MAXDEG 512
#define NBW    1568
#define GRID   148
#define TPB    256

#define VREAD(x) (*(volatile int*)&(x))

// ---------------- scratch (static device globals, zero-initialized) ---------
__device__ int      g_uslot[NMAXC];     // 0=free, -1=pending, k+1 = slot k
__device__ unsigned g_tbit[NBW];
__device__ int      g_l1_src[MAXL1];
__device__ int      g_l1_us[MAXL1];
__device__ int      g_e1_dstn[MAXE1];
__device__ int      g_e1_dst[MAXE1];
__device__ int      g_e1_src[MAXE1];
__device__ int      g_e1_us[MAXE1];
__device__ int      g_ulist[MAXU];
__device__ int      g_cnt[4];           // 0=l1 1=tgt 2=u 3=e1 (self-cleaned)
__device__ __align__(16) float g_h0[MAXU][FDIM];
__device__ float    g_al0[MAXU][2*NH];
__device__ __align__(16) float g_h1[MAXT][FDIM];
__device__ float    g_al1[MAXT][2*NH];
__device__ float    g_mlp[DIN];
__device__ int      g_barc;             // barrier arrive counter (self-resets)
__device__ int      g_barg;             // barrier generation (monotonic)

// ---------------- helpers ---------------------------------------------------
__device__ __forceinline__ float warp_sum(float v) {
    #pragma unroll
    for (int o = 16; o; o >>= 1) v += __shfl_xor_sync(0xffffffffu, v, o);
    return v;
}
__device__ __forceinline__ float warp_max(float v) {
    #pragma unroll
    for (int o = 16; o; o >>= 1) v = fmaxf(v, __shfl_xor_sync(0xffffffffu, v, o));
    return v;
}
__device__ __forceinline__ float lrelu(float x) { return x > 0.f ? x : 0.2f * x; }

__device__ __forceinline__ void s1_hit(int d, int tgt, const int* __restrict__ src, int e) {
    if (d == tgt) {
        int p = atomicAdd(&g_cnt[0], 1);
        if (p < MAXL1) g_l1_src[p] = src[e];
    }
}
__device__ __forceinline__ void s2_hit(int d, int N, const int* __restrict__ src, int e) {
    if ((unsigned)d < (unsigned)N) {
        if ((g_tbit[d >> 5] >> (d & 31)) & 1u) {
            int p = atomicAdd(&g_cnt[3], 1);
            if (p < MAXE1) { g_e1_dstn[p] = d; g_e1_src[p] = src[e]; }
        }
    }
}

// Grid barrier: last-arriving CTA runs TAILCODE (block-parallel) before release.
#define GBAR(...) do {                                                         \
    __syncthreads();                                                           \
    if (threadIdx.x == 0) {                                                    \
        __threadfence();                                                       \
        s_gen  = VREAD(g_barg);                                                \
        s_tailf = (atomicAdd(&g_barc, 1) == GRID - 1);                         \
        if (s_tailf) __threadfence();                                          \
    }                                                                          \
    __syncthreads();                                                           \
    if (s_tailf) {                                                             \
        { __VA_ARGS__ }                                                        \
        __syncthreads();                                                       \
        if (threadIdx.x == 0) {                                                \
            g_barc = 0;                                                        \
            __threadfence();                                                   \
            *(volatile int*)&g_barg = s_gen + 1;                               \
        }                                                                      \
        __syncthreads();                                                       \
    } else {                                                                   \
        if (threadIdx.x == 0) {                                                \
            while (VREAD(g_barg) == s_gen) __nanosleep(32);                    \
            __threadfence();                                                   \
        }                                                                      \
        __syncthreads();                                                       \
    }                                                                          \
} while (0)

// ---------------- the megakernel --------------------------------------------
__global__ void __launch_bounds__(TPB) mega(
    const int* __restrict__ y, const int* __restrict__ src,
    const int* __restrict__ dst, const int4* __restrict__ dst4, int E4,
    const float* __restrict__ emb, const float* __restrict__ W0,
    const float* __restrict__ as0, const float* __restrict__ ad0,
    const float* __restrict__ b0,  const float* __restrict__ W1,
    const float* __restrict__ as1, const float* __restrict__ ad1,
    const float* __restrict__ b1,  const float* __restrict__ pw1,
    const float* __restrict__ pb1, const float* __restrict__ pw2,
    const float* __restrict__ pb2, float* __restrict__ out,
    int N, int E, int V)
{
    __shared__ int    s_gen, s_tailf;
    __shared__ int    s_eidx[MAXDEG];
    __shared__ int    s_ecnt;
    __shared__ float  s_e[(MAXDEG + 1) * NH];          // softmax energies/alphas
    __shared__ __align__(16) float s_fs[FDIM];         // input vector for matvecs
    __shared__ __align__(16) float s_vec[FDIM];        // matvec output
    __shared__ float4 s_mv[4][64];                     // split-k partials
    __shared__ __align__(16) float s_x3[3][DIN];       // P3: up to 3 emb rows
    __shared__ float4 s_mv3[3][4][64];                 // P3: per-node partials
    __shared__ float  s_red[8][2];
    __shared__ float  s_snorm;

    const int tid  = threadIdx.x;
    const int bid  = blockIdx.x;
    const int wid  = tid >> 5, lane = tid & 31;
    const int nth  = GRID * TPB;
    const int gtid = bid * TPB + tid;

    // ======== P1: scan edges for dst == N-1 =================================
    {
        int tgt = N - 1;
        if (E4 > 0) {
            for (int i = gtid; i < E4; i += 4 * nth) {
                int ib = i + nth, ic = i + 2 * nth, id = i + 3 * nth;
                int4 A = dst4[i];
                int4 B = ib < E4 ? dst4[ib] : make_int4(-1,-1,-1,-1);
                int4 C = ic < E4 ? dst4[ic] : make_int4(-1,-1,-1,-1);
                int4 D = id < E4 ? dst4[id] : make_int4(-1,-1,-1,-1);
                s1_hit(A.x, tgt, src, 4*i);   s1_hit(A.y, tgt, src, 4*i+1);
                s1_hit(A.z, tgt, src, 4*i+2); s1_hit(A.w, tgt, src, 4*i+3);
                s1_hit(B.x, tgt, src, 4*ib);  s1_hit(B.y, tgt, src, 4*ib+1);
                s1_hit(B.z, tgt, src, 4*ib+2);s1_hit(B.w, tgt, src, 4*ib+3);
                s1_hit(C.x, tgt, src, 4*ic);  s1_hit(C.y, tgt, src, 4*ic+1);
                s1_hit(C.z, tgt, src, 4*ic+2);s1_hit(C.w, tgt, src, 4*ic+3);
                s1_hit(D.x, tgt, src, 4*id);  s1_hit(D.y, tgt, src, 4*id+1);
                s1_hit(D.z, tgt, src, 4*id+2);s1_hit(D.w, tgt, src, 4*id+3);
            }
            for (int e = 4 * E4 + gtid; e < E; e += nth) s1_hit(dst[e], tgt, src, e);
        } else {
            for (int e = gtid; e < E; e += nth) s1_hit(dst[e], tgt, src, e);
        }
    }
    GBAR({   // ---- prep1: claim 1-hop targets, build bitmap, resolve slots
        int n1 = min(VREAD(g_cnt[0]), MAXL1);
        if (tid == 0) {
            g_uslot[N - 1] = 1;
            g_ulist[0] = N - 1;
            g_cnt[2] = 1;
            atomicOr(&g_tbit[(N - 1) >> 5], 1u << ((N - 1) & 31));
        }
        __syncthreads();
        for (int i = tid; i < n1; i += TPB) {
            int s = g_l1_src[i];
            if (atomicCAS(&g_uslot[s], 0, -1) == 0) {
                int p = atomicAdd(&g_cnt[2], 1);
                g_uslot[s] = p + 1;
                if (p < MAXU) g_ulist[p] = s;
                atomicOr(&g_tbit[s >> 5], 1u << (s & 31));
            }
        }
        __syncthreads();
        if (tid == 0) g_cnt[1] = g_cnt[2];
        for (int i = tid; i < n1; i += TPB)
            g_l1_us[i] = g_uslot[g_l1_src[i]] - 1;
    });

    // ======== P2: scan edges for dst in target set ==========================
    {
        if (E4 > 0) {
            for (int i = gtid; i < E4; i += 4 * nth) {
                int ib = i + nth, ic = i + 2 * nth, id = i + 3 * nth;
                int4 A = dst4[i];
                int4 B = ib < E4 ? dst4[ib] : make_int4(-1,-1,-1,-1);
                int4 C = ic < E4 ? dst4[ic] : make_int4(-1,-1,-1,-1);
                int4 D = id < E4 ? dst4[id] : make_int4(-1,-1,-1,-1);
                s2_hit(A.x, N, src, 4*i);   s2_hit(A.y, N, src, 4*i+1);
                s2_hit(A.z, N, src, 4*i+2); s2_hit(A.w, N, src, 4*i+3);
                s2_hit(B.x, N, src, 4*ib);  s2_hit(B.y, N, src, 4*ib+1);
                s2_hit(B.z, N, src, 4*ib+2);s2_hit(B.w, N, src, 4*ib+3);
                s2_hit(C.x, N, src, 4*ic);  s2_hit(C.y, N, src, 4*ic+1);
                s2_hit(C.z, N, src, 4*ic+2);s2_hit(C.w, N, src, 4*ic+3);
                s2_hit(D.x, N, src, 4*id);  s2_hit(D.y, N, src, 4*id+1);
                s2_hit(D.z, N, src, 4*id+2);s2_hit(D.w, N, src, 4*id+3);
            }
            for (int e = 4 * E4 + gtid; e < E; e += nth) s2_hit(dst[e], N, src, e);
        } else {
            for (int e = gtid; e < E; e += nth) s2_hit(dst[e], N, src, e);
        }
    }
    GBAR({   // ---- prep2: claim 2-hop frontier, resolve e1 slots
        int n = min(VREAD(g_cnt[3]), MAXE1);
        for (int i = tid; i < n; i += TPB) {
            int s = g_e1_src[i];
            if (atomicCAS(&g_uslot[s], 0, -1) == 0) {
                int p = atomicAdd(&g_cnt[2], 1);
                g_uslot[s] = p + 1;
                if (p < MAXU) g_ulist[p] = s;
            }
        }
        __syncthreads();
        for (int i = tid; i < n; i += TPB) {
            g_e1_us[i]  = g_uslot[g_e1_src[i]] - 1;
            g_e1_dst[i] = g_uslot[g_e1_dstn[i]] - 1;
        }
    });

    // ======== P3: h0 = emb[y]@W0 (+ al0), CTA per ≤3 nodes, 1 W0 pass =======
    {
        int ucnt = min(VREAD(g_cnt[2]), MAXU);
        const float4* W04 = (const float4*)W0;      // [DIN][64]
        int cg = tid & 63, kq = tid >> 6;
        for (int base = bid; base < ucnt; base += 3 * GRID) {
            int cnt = 1;
            if (base + GRID     < ucnt) cnt = 2;
            if (base + 2 * GRID < ucnt) cnt = 3;

            // load up to 3 emb rows (3 nodes x 16 float4)
            if (tid < 48) {
                int j = tid >> 4, q = tid & 15;
                int u = base + j * GRID;
                if (u < ucnt) {
                    int node = g_ulist[u];
                    ((float4*)s_x3[j])[q] =
                        ((const float4*)(emb + (long long)y[node] * DIN))[q];
                }
            }
            __syncthreads();

            // single pass over W0: 1 load, up to 3 FMA4 per k
            float4 a0 = make_float4(0.f,0.f,0.f,0.f);
            float4 a1 = make_float4(0.f,0.f,0.f,0.f);
            float4 a2 = make_float4(0.f,0.f,0.f,0.f);
            #pragma unroll
            for (int k = kq * 16; k < kq * 16 + 16; k++) {
                float4 w = W04[k * 64 + cg];
                float x0 = s_x3[0][k], x1 = s_x3[1][k], x2 = s_x3[2][k];
                a0.x += x0 * w.x; a0.y += x0 * w.y; a0.z += x0 * w.z; a0.w += x0 * w.w;
                a1.x += x1 * w.x; a1.y += x1 * w.y; a1.z += x1 * w.z; a1.w += x1 * w.w;
                a2.x += x2 * w.x; a2.y += x2 * w.y; a2.z += x2 * w.z; a2.w += x2 * w.w;
            }
            s_mv3[0][kq][cg] = a0;
            s_mv3[1][kq][cg] = a1;
            s_mv3[2][kq][cg] = a2;
            __syncthreads();

            // per-node epilogue: combine partials, store h0, compute al0
            for (int j = 0; j < cnt; j++) {
                int u = base + j * GRID;
                if (tid < 64) {
                    float4 r0 = s_mv3[j][0][tid], r1 = s_mv3[j][1][tid];
                    float4 r2 = s_mv3[j][2][tid], r3 = s_mv3[j][3][tid];
                    float4 r = make_float4(r0.x+r1.x+r2.x+r3.x, r0.y+r1.y+r2.y+r3.y,
                                           r0.z+r1.z+r2.z+r3.z, r0.w+r1.w+r2.w+r3.w);
                    ((float4*)s_vec)[tid] = r;
                    ((float4*)(g_h0[u]))[tid] = r;
                }
                __syncthreads();
                float hv = s_vec[tid];
                float ps = warp_sum(hv * as0[tid]);
                float pd = warp_sum(hv * ad0[tid]);
                if (lane == 0) { s_red[wid][0] = ps; s_red[wid][1] = pd; }
                __syncthreads();
                if (tid < 2 * NH) {
                    int h = tid & 3;
                    g_al0[u][tid] = (tid < NH) ? (s_red[2*h][0] + s_red[2*h+1][0])
                                               : (s_red[2*h][1] + s_red[2*h+1][1]);
                }
                __syncthreads();
            }
        }
    }
    GBAR({});

    // ======== P4: layer-0 agg + layer-1 transform (CTA t < tcnt) ============
    {
        int tcnt = VREAD(g_cnt[1]);
        int e1n  = min(VREAD(g_cnt[3]), MAXE1);
        if (bid < tcnt) {
            int t = bid;
            if (tid == 0) s_ecnt = 0;
            __syncthreads();
            for (int i = tid; i < e1n; i += TPB)
                if (g_e1_dst[i] == t) {
                    int p = atomicAdd(&s_ecnt, 1);
                    if (p < MAXDEG) s_eidx[p] = g_e1_us[i];
                }
            __syncthreads();
            int ne = min(s_ecnt, MAXDEG);       // +1 implicit self-loop

            float ald0 = g_al0[t][NH + 0], ald1 = g_al0[t][NH + 1];
            float ald2 = g_al0[t][NH + 2], ald3 = g_al0[t][NH + 3];
            for (int idx = tid; idx < (ne + 1) * NH; idx += TPB) {
                int i = idx >> 2, h = idx & 3;
                int us = (i == ne) ? t : s_eidx[i];
                float ad = (h == 0) ? ald0 : (h == 1) ? ald1 : (h == 2) ? ald2 : ald3;
                s_e[idx] = lrelu(g_al0[us][h] + ad);
            }
            __syncthreads();
            if (wid < NH) {       // warp per head: max, exp, normalize
                int h = wid;
                float m = -3.0e38f;
                for (int i = lane; i <= ne; i += 32) m = fmaxf(m, s_e[i*4 + h]);
                m = warp_max(m);
                float d = 0.f;
                for (int i = lane; i <= ne; i += 32) {
                    float ev = expf(s_e[i*4 + h] - m);
                    s_e[i*4 + h] = ev;
                    d += ev;
                }
                d = warp_sum(d) + 1e-16f;
                float inv = 1.f / d;
                for (int i = lane; i <= ne; i += 32) s_e[i*4 + h] *= inv;
            }
            __syncthreads();

            // weighted feature sum (2 accumulators for load ILP) + ELU + norm
            int c = tid, head = c >> 6;
            float acc = 0.f, acc2 = 0.f;
            {
                int i = 0;
                for (; i + 1 < ne; i += 2) {
                    int us0 = s_eidx[i], us1 = s_eidx[i + 1];
                    acc  += s_e[i*4 + head]       * g_h0[us0][c];
                    acc2 += s_e[(i + 1)*4 + head] * g_h0[us1][c];
                }
                for (; i < ne; i++)
                    acc += s_e[i*4 + head] * g_h0[s_eidx[i]][c];
                acc += s_e[ne*4 + head] * g_h0[t][c];   // self loop
                acc += acc2;
            }
            acc += b0[c];
            acc = acc > 0.f ? acc : expm1f(acc);
            float ss = warp_sum(acc * acc);
            if (lane == 0) s_red[wid][0] = ss;
            __syncthreads();
            if (tid == 0) {
                float s = 0.f;
                for (int w = 0; w < 8; w++) s += s_red[w][0];
                s_snorm = fmaxf(sqrtf(s), 1e-12f);
            }
            __syncthreads();
            s_fs[c] = acc / s_snorm;
            __syncthreads();

            // h1 = fs @ W1 (split-k float4) + al1
            {
                const float4* W14 = (const float4*)W1;  // [256][64]
                int cg = tid & 63, kq = tid >> 6;
                float4 a = make_float4(0.f, 0.f, 0.f, 0.f);
                #pragma unroll 16
                for (int k = kq * 64; k < kq * 64 + 64; k++) {
                    float x = s_fs[k];
                    float4 w = W14[k * 64 + cg];
                    a.x += x * w.x; a.y += x * w.y; a.z += x * w.z; a.w += x * w.w;
                }
                s_mv[kq][cg] = a;
                __syncthreads();
                if (tid < 64) {
                    float4 r0 = s_mv[0][tid], r1 = s_mv[1][tid];
                    float4 r2 = s_mv[2][tid], r3 = s_mv[3][tid];
                    float4 r = make_float4(r0.x+r1.x+r2.x+r3.x, r0.y+r1.y+r2.y+r3.y,
                                           r0.z+r1.z+r2.z+r3.z, r0.w+r1.w+r2.w+r3.w);
                    ((float4*)s_vec)[tid] = r;
                    ((float4*)(g_h1[t]))[tid] = r;
                }
                __syncthreads();
                float hv = s_vec[tid];
                float ps = warp_sum(hv * as1[tid]);
                float pd = warp_sum(hv * ad1[tid]);
                if (lane == 0) { s_red[wid][0] = ps; s_red[wid][1] = pd; }
                __syncthreads();
                if (tid < 2 * NH) {
                    int h = tid & 3;
                    g_al1[t][tid] = (tid < NH) ? (s_red[2*h][0] + s_red[2*h+1][0])
                                               : (s_red[2*h][1] + s_red[2*h+1][1]);
                }
            }
        }
    }
    GBAR({   // ---- final: layer-1 aggregation at N-1 + ctx MLP
        int n1 = min(VREAD(g_cnt[0]), MAXDEG);

        float ald0 = g_al1[0][NH + 0], ald1 = g_al1[0][NH + 1];
        float ald2 = g_al1[0][NH + 2], ald3 = g_al1[0][NH + 3];
        for (int idx = tid; idx < (n1 + 1) * NH; idx += TPB) {
            int i = idx >> 2, h = idx & 3;
            int us = (i == n1) ? 0 : g_l1_us[i];
            float ad = (h == 0) ? ald0 : (h == 1) ? ald1 : (h == 2) ? ald2 : ald3;
            s_e[idx] = lrelu(g_al1[us][h] + ad);
        }
        __syncthreads();
        if (wid < NH) {
            int h = wid;
            float m = -3.0e38f;
            for (int i = lane; i <= n1; i += 32) m = fmaxf(m, s_e[i*4 + h]);
            m = warp_max(m);
            float d = 0.f;
            for (int i = lane; i <= n1; i += 32) {
                float ev = expf(s_e[i*4 + h] - m);
                s_e[i*4 + h] = ev;
                d += ev;
            }
            d = warp_sum(d) + 1e-16f;
            float inv = 1.f / d;
            for (int i = lane; i <= n1; i += 32) s_e[i*4 + h] *= inv;
        }
        __syncthreads();

        int c = tid, head = c >> 6;
        float acc = 0.f, acc2 = 0.f;
        {
            int i = 0;
            for (; i + 1 < n1; i += 2) {
                int us0 = g_l1_us[i], us1 = g_l1_us[i + 1];
                acc  += s_e[i*4 + head]       * g_h1[us0][c];
                acc2 += s_e[(i + 1)*4 + head] * g_h1[us1][c];
            }
            for (; i < n1; i++)
                acc += s_e[i*4 + head] * g_h1[g_l1_us[i]][c];
            acc += s_e[n1*4 + head] * g_h1[0][c];     // self loop (slot 0 = N-1)
            acc += acc2;
        }
        acc += b1[c];
        acc = acc > 0.f ? acc : expm1f(acc);
        float ss = warp_sum(acc * acc);
        if (lane == 0) s_red[wid][0] = ss;
        __syncthreads();
        if (tid == 0) {
            float s = 0.f;
            for (int w = 0; w < 8; w++) s += s_red[w][0];
            s_snorm = fmaxf(sqrtf(s), 1e-12f);
        }
        __syncthreads();
        s_fs[c] = acc / s_snorm;
        __syncthreads();

        // mlp = relu(ctx @ pw1 + pb1): thread = (col, k-quarter), k 64 each
        {
            int col = tid & 63, kq = tid >> 6;
            float a = 0.f;
            #pragma unroll 16
            for (int k = kq * 64; k < kq * 64 + 64; k++)
                a += s_fs[k] * pw1[k * DIN + col];
            s_mv[kq][col].x = a;
            __syncthreads();
            if (tid < DIN) {
                float v = pb1[tid] + s_mv[0][tid].x + s_mv[1][tid].x
                                   + s_mv[2][tid].x + s_mv[3][tid].x;
                g_mlp[tid] = fmaxf(v, 0.f);
            }
        }
    });

    // ======== P5: out = mlp @ pw2 + pb2 (+ cleanup by last CTA) =============
    {
        if (bid == GRID - 1) {
            int ucnt = min(VREAD(g_cnt[2]), MAXU);
            int tcnt = VREAD(g_cnt[1]);
            for (int i = tid; i < ucnt; i += TPB) {
                int node = g_ulist[i];
                g_uslot[node] = 0;
                if (i < tcnt) atomicAnd(&g_tbit[node >> 5], ~(1u << (node & 31)));
            }
            __syncthreads();
            if (tid == 0) {
                g_cnt[0] = 0; g_cnt[1] = 0; g_cnt[2] = 0; g_cnt[3] = 0;
                __threadfence();
            }
        }

        if (tid < DIN) s_fs[tid] = g_mlp[tid];
        __syncthreads();

        if ((V & 3) == 0) {
            int V4 = V >> 2;
            const float4* pw24 = (const float4*)pw2;
            const float4* pb24 = (const float4*)pb2;
            float4* out4 = (float4*)out;
            int chunk = (V4 + GRID - 1) / GRID;
            int lo = bid * chunk;
            int hi = min(lo + chunk, V4);
            for (int v = lo + tid; v < hi; v += TPB) {
                float4 acc = pb24[v];
                #pragma unroll 16
                for (int j = 0; j < DIN; j++) {
                    float w = s_fs[j];
                    float4 p = pw24[(size_t)j * V4 + v];
                    acc.x += w * p.x; acc.y += w * p.y;
                    acc.z += w * p.z; acc.w += w * p.w;
                }
                out4[v] = acc;
            }
        } else {
            int chunk = (V + GRID - 1) / GRID;
            int lo = bid * chunk;
            int hi = min(lo + chunk, V);
            for (int v = lo + tid; v < hi; v += TPB) {
                float acc = pb2[v];
                for (int j = 0; j < DIN; j++) acc += s_fs[j] * pw2[(size_t)j * V + v];
                out[v] = acc;
            }
        }
    }
}

// ---------------- launcher ---------------------------------------------------
extern "C" void kernel_launch(void* const* d_in, const int* in_sizes, int n_in,
                              void* d_out, int out_size) {
    const int*   y   = (const int*)  d_in[0];
    const int*   ei  = (const int*)  d_in[1];
    const float* emb = (const float*)d_in[2];
    const float* W0  = (const float*)d_in[3];
    const float* as0 = (const float*)d_in[4];
    const float* ad0 = (const float*)d_in[5];
    const float* b0  = (const float*)d_in[6];
    const float* W1  = (const float*)d_in[7];
    const float* as1 = (const float*)d_in[8];
    const float* ad1 = (const float*)d_in[9];
    const float* b1  = (const float*)d_in[10];
    const float* pw1 = (const float*)d_in[11];
    const float* pb1 = (const float*)d_in[12];
    const float* pw2 = (const float*)d_in[13];
    const float* pb2 = (const float*)d_in[14];
    float* out = (float*)d_out;

    int N = in_sizes[0];
    int E = in_sizes[1] / 2;
    int V = out_size;
    const int* srcp = ei;
    const int* dstp = ei + E;
    int E4 = (((size_t)dstp & 15) == 0) ? (E >> 2) : 0;
    const int4* dst4 = (const int4*)dstp;

    mega<<<GRID, TPB>>>(y, srcp, dstp, dst4, E4,
                        emb, W0, as0, ad0, b0, W1, as1, ad1, b1,
                        pw1, pb1, pw2, pb2, out, N, E, V);
}